// round 11
// baseline (speedup 1.0000x reference)
#include <cuda_runtime.h>

#define NUM_GRAPHS 512
#define D 128
#define H 256
#define GPB 4             // graphs per block
#define T 1024            // threads per block (32 warps)

// ---------------------------------------------------------------------------
__device__ __forceinline__ void facc(float4& a, float4 v) {
    a.x += v.x; a.y += v.y; a.z += v.z; a.w += v.w;
}

// ---------------------------------------------------------------------------
// ONE kernel: per-block segment-sum of its own 4 graphs (contiguous rows of x
// because batch is sorted) -> 2-layer MLP on the 4 graph vectors -> confidence
// head -> scatter to all nodes of those graphs. No global scratch.
__global__ __launch_bounds__(T) void fused_kernel(
        const float4* __restrict__ x4, const int* __restrict__ batch, int N,
        const float* __restrict__ W1, const float* __restrict__ b1,
        const float* __restrict__ W2, const float* __restrict__ b2,
        const float* __restrict__ Wc, const float* __restrict__ bc,
        float* __restrict__ out) {
    // sBuf: phase 1 = 32 warp-partial rows [32][128]; phase 2 = sP [4][4][256]
    __shared__ float sBuf[4096];                     // 16 KB
    __shared__ float sS[GPB][D];                     // 2 KB
    __shared__ float sH[GPB][H];                     // 4 KB
    __shared__ float sRed[GPB][8];
    __shared__ int   sbound[GPB + 1];
    __shared__ float sv[GPB];
    __shared__ int   sSamp[1024];                    // 4 KB batch samples

    const int g0   = blockIdx.x * GPB;
    const int t    = threadIdx.x;
    const int col  = t & (H - 1);
    const int qr   = t >> 8;
    const int lane = t & 31;
    const int warp = t >> 5;            // 0..31

    // ---- Bounds round 1: sample batch at 1024 evenly spaced points ----
    {
        int idx = (int)(((long long)t * N) >> 10);   // t*N/1024, monotone
        sSamp[t] = batch[idx];
    }
    __syncthreads();

    // ---- Bounds round 2: warps 0..GPB resolve lb(g0+warp) exactly ----
    if (warp <= GPB) {
        const int v = g0 + warp;
        // count samples < v (samples are sorted)
        int cnt = 0;
        #pragma unroll
        for (int k = 0; k < 32; k++)
            cnt += (sSamp[lane + k * 32] < v) ? 1 : 0;
        #pragma unroll
        for (int s = 16; s > 0; s >>= 1)
            cnt += __shfl_down_sync(0xFFFFFFFFu, cnt, s);
        int c = __shfl_sync(0xFFFFFFFFu, cnt, 0);
        // bracket [loH, hiH) containing lb(v); width <= ceil(N/1024)
        int loH = (c > 0)    ? (int)(((long long)(c - 1) * N) >> 10) + 1 : 0;
        int hiH = (c < 1024) ? (int)(((long long)c * N) >> 10) + 1 : N;
        // exact: count elements < v in bracket (independent loads, 1 round)
        int myc = 0;
        for (int base = loH; base < hiH; base += 128) {
            #pragma unroll
            for (int k = 0; k < 4; k++) {
                int i = base + k * 32 + lane;
                myc += (i < hiH && batch[i] < v) ? 1 : 0;
            }
        }
        #pragma unroll
        for (int s = 16; s > 0; s >>= 1)
            myc += __shfl_down_sync(0xFFFFFFFFu, myc, s);
        if (lane == 0) sbound[warp] = loH + myc;
    }
    __syncthreads();

    // ---- Segment sum: 8 warps per graph, CONTIGUOUS per-warp chunks.
    //      Lane owns one float4 column chunk; 4-wide unrolled batches with
    //      unroll 2 -> up to 8 independent LDG.128 in flight per warp. ----
    {
        const int q   = warp >> 3;      // graph 0..3
        const int sub = warp & 7;       // 0..7
        const int lo = sbound[q], hi = sbound[q + 1];
        const int len   = hi - lo;
        const int chunk = (len + 7) >> 3;
        const int s = lo + sub * chunk;
        const int e = min(s + chunk, hi);

        float4 a0 = make_float4(0.f, 0.f, 0.f, 0.f);
        float4 a1 = a0, a2 = a0, a3 = a0;
        int r = s;
        #pragma unroll 2
        for (; r + 3 < e; r += 4) {
            float4 v0 = x4[(size_t)(r + 0) * (D / 4) + lane];
            float4 v1 = x4[(size_t)(r + 1) * (D / 4) + lane];
            float4 v2 = x4[(size_t)(r + 2) * (D / 4) + lane];
            float4 v3 = x4[(size_t)(r + 3) * (D / 4) + lane];
            facc(a0, v0); facc(a1, v1); facc(a2, v2); facc(a3, v3);
        }
        for (; r < e; r++)
            facc(a0, x4[(size_t)r * (D / 4) + lane]);
        facc(a0, a1); facc(a2, a3); facc(a0, a2);

        *reinterpret_cast<float4*>(&sBuf[warp * D + lane * 4]) = a0;
    }
    __syncthreads();

    // Reduce 8 warp-partials per graph -> sS (512 threads, 1 col each)
    if (t < GPB * D) {
        const int q = t >> 7, c = t & (D - 1);
        float v = 0.f;
        #pragma unroll
        for (int w = 0; w < 8; w++) v += sBuf[(q * 8 + w) * D + c];
        sS[q][c] = v;
    }
    __syncthreads();

    float* sP = sBuf;   // reuse as [4 quarters][GPB][H]

    // ---- Layer 1: qr owns k in [qr*32, qr*32+32) ----
    float acc[GPB];
    #pragma unroll
    for (int q = 0; q < GPB; q++) acc[q] = 0.f;

    #pragma unroll
    for (int c = 0; c < 2; c++) {
        const int kb = qr * 32 + c * 16;
        float w[16];
        #pragma unroll
        for (int j = 0; j < 16; j++) w[j] = W1[(kb + j) * H + col];
        #pragma unroll
        for (int j = 0; j < 16; j += 4) {
            float4 s0 = *reinterpret_cast<const float4*>(&sS[0][kb + j]);
            float4 s1 = *reinterpret_cast<const float4*>(&sS[1][kb + j]);
            float4 s2 = *reinterpret_cast<const float4*>(&sS[2][kb + j]);
            float4 s3 = *reinterpret_cast<const float4*>(&sS[3][kb + j]);
            #pragma unroll
            for (int kk = 0; kk < 4; kk++) {
                float ww = w[j + kk];
                acc[0] = fmaf((&s0.x)[kk], ww, acc[0]);
                acc[1] = fmaf((&s1.x)[kk], ww, acc[1]);
                acc[2] = fmaf((&s2.x)[kk], ww, acc[2]);
                acc[3] = fmaf((&s3.x)[kk], ww, acc[3]);
            }
        }
    }
    #pragma unroll
    for (int q = 0; q < GPB; q++) sP[(qr * GPB + q) * H + col] = acc[q];
    __syncthreads();

    // combine quarters -> h1 = relu(b1 + Σp) * cnt  (cnt scale = agg2)
    {
        int q = t >> 8, c = t & (H - 1);
        float cnt = (float)(sbound[q + 1] - sbound[q]);
        float h = b1[c] + sP[(0 * GPB + q) * H + c] + sP[(1 * GPB + q) * H + c]
                        + sP[(2 * GPB + q) * H + c] + sP[(3 * GPB + q) * H + c];
        sH[q][c] = fmaxf(h, 0.f) * cnt;
    }
    __syncthreads();

    // ---- Layer 2: qr owns k in [qr*64, qr*64+64) ----
    #pragma unroll
    for (int q = 0; q < GPB; q++) acc[q] = 0.f;

    #pragma unroll
    for (int c = 0; c < 4; c++) {
        const int kb = qr * 64 + c * 16;
        float w[16];
        #pragma unroll
        for (int j = 0; j < 16; j++) w[j] = W2[(kb + j) * H + col];
        #pragma unroll
        for (int j = 0; j < 16; j += 4) {
            float4 s0 = *reinterpret_cast<const float4*>(&sH[0][kb + j]);
            float4 s1 = *reinterpret_cast<const float4*>(&sH[1][kb + j]);
            float4 s2 = *reinterpret_cast<const float4*>(&sH[2][kb + j]);
            float4 s3 = *reinterpret_cast<const float4*>(&sH[3][kb + j]);
            #pragma unroll
            for (int kk = 0; kk < 4; kk++) {
                float ww = w[j + kk];
                acc[0] = fmaf((&s0.x)[kk], ww, acc[0]);
                acc[1] = fmaf((&s1.x)[kk], ww, acc[1]);
                acc[2] = fmaf((&s2.x)[kk], ww, acc[2]);
                acc[3] = fmaf((&s3.x)[kk], ww, acc[3]);
            }
        }
    }
    #pragma unroll
    for (int q = 0; q < GPB; q++) sP[(qr * GPB + q) * H + col] = acc[q];
    __syncthreads();

    // ---- Head: h2 = relu(b2 + Σp); c = Σ_col h2*Wc; softplus-sigmoid ----
    {
        int q = t >> 8, c = t & (H - 1);
        float h = b2[c] + sP[(0 * GPB + q) * H + c] + sP[(1 * GPB + q) * H + c]
                        + sP[(2 * GPB + q) * H + c] + sP[(3 * GPB + q) * H + c];
        float v = fmaxf(h, 0.f) * Wc[c];
        #pragma unroll
        for (int s = 16; s > 0; s >>= 1)
            v += __shfl_down_sync(0xFFFFFFFFu, v, s);
        if (lane == 0) sRed[q][warp & 7] = v;
    }
    __syncthreads();

    if (t < GPB) {
        float c = bc[0];
        #pragma unroll
        for (int w = 0; w < 8; w++) c += sRed[t][w];
        float sp = fmaxf(c, 0.f) + log1pf(expf(-fabsf(c)));
        sv[t] = sp / (1.f + sp);
    }
    __syncthreads();

    // ---- Scatter over this block's contiguous node range ----
    const int lo = sbound[0], hi = sbound[GPB];
    for (int n = lo + t; n < hi; n += T)
        out[n] = sv[batch[n] - g0];
}

// ---------------------------------------------------------------------------
extern "C" void kernel_launch(void* const* d_in, const int* in_sizes, int n_in,
                              void* d_out, int out_size) {
    const float* x     = (const float*)d_in[0];
    const int*   batch = (const int*)d_in[1];
    const float* W1    = (const float*)d_in[2];
    const float* b1    = (const float*)d_in[3];
    const float* W2    = (const float*)d_in[4];
    const float* b2    = (const float*)d_in[5];
    const float* Wc    = (const float*)d_in[6];
    const float* bc    = (const float*)d_in[7];
    float*       out   = (float*)d_out;

    const int N = in_sizes[1];

    fused_kernel<<<NUM_GRAPHS / GPB, T>>>(
        reinterpret_cast<const float4*>(x), batch, N,
        W1, b1, W2, b2, Wc, bc, out);
}